// round 10
// baseline (speedup 1.0000x reference)
#include <cuda_runtime.h>
#include <cuda_fp16.h>

// Inputs (harness upcasts f16 arrays to f32):
//   x[16384,4096] f32(f16-valued), pairs[8,4096] i32, theta[8,2048] f32,
//   scales[1,4096] f32, out f32.
// Reference rounds to f16 after EVERY op -> *_rn intrinsics, no contraction.
// Chained schedule (rel_err=0.0 since R8): thread keeps one rotation output in
// a register across layers (1 LDS + 1 STS per pair instead of 2+2).
// R10: prep_sched walk uses register bitmasks + direct partner map (no local
// memory, 1 dependent LDS/hop); coefficients stored pre-broadcast (Coef4).
#define DIMV   4096
#define KROT   8
#define GRP    128
#define NGRP   32
#define ILG    64
#define ROWS   8
#define TPB    512

// ---- schedule tables consumed by prep_coef / rot_kernel ----
__device__ unsigned char d_pA[KROT][ILG];     // pair a-channel (ref orientation)
__device__ unsigned char d_pil[KROT][ILG];    // pair handled by slot s at layer k
__device__ unsigned char d_vch[KROT][ILG];    // channel held entering layer k
__device__ unsigned char d_keepv[KROT][ILG];  // keep held-side output?
__device__ unsigned g_pt4[KROT * 16];         // packed READ (partner) channels
__device__ unsigned g_wc4[KROT * 16];         // packed WRITE channels
__device__ unsigned g_v0p[16];                // packed initial held channels
__device__ unsigned g_v7p[16];                // packed held channels at layer 7
struct __align__(16) Coef4 { __half2 k1, k2, w1, w2; };  // pre-broadcast
__device__ Coef4 g_cs4[KROT * ILG * NGRP];

struct __align__(16) H8 { __half2 r01, r23, r45, r67; };  // 8 rows of a channel

// slot(c,g): conflict-free when lanes span g at warp-uniform c (rotation)
// and when lanes span c>>2 at fixed g (transpose).
__device__ __forceinline__ int slot(int c, int g) {
    return (c << 5) + (g ^ (c >> 2));
}

// ---- build chain schedule: one block, shared tables, register bitmask walks ----
__global__ void __launch_bounds__(TPB)
prep_sched(const int* __restrict__ pairs) {
    __shared__ unsigned char sA[KROT][ILG], sB[KROT][ILG];
    __shared__ unsigned char sOf[KROT][GRP];
    __shared__ unsigned char sNxt[KROT][GRP];   // direct partner map
    __shared__ unsigned char sM[KROT][ILG];
    __shared__ unsigned char sPil[KROT][ILG], sVch[KROT][ILG], sKeep[KROT][ILG];
    const int tid = threadIdx.x;

    // Phase 1: load all pairs; build pair->channels, channel->pair, channel->partner.
    {
        int k = tid >> 6, il = tid & 63;
        int a = pairs[k * DIMV + 2 * il];
        int b = pairs[k * DIMV + 2 * il + 1];
        sA[k][il] = (unsigned char)a;
        sB[k][il] = (unsigned char)b;
        sOf[k][a] = (unsigned char)il;
        sOf[k][b] = (unsigned char)il;
        sNxt[k][a] = (unsigned char)b;
        sNxt[k][b] = (unsigned char)a;
    }
    __syncthreads();

    // Phase 2: matching layer k -> k+1 (7 parallel threads). Even-cycle walk,
    // alternating edges; visited bits in two 64-bit REGISTERS (no local mem),
    // one dependent LDS per hop via sNxt.
    if (tid < KROT - 1) {
        const int k = tid;
        unsigned long long visLo = 0ull, visHi = 0ull;
        for (int c0 = 0; c0 < GRP; c0++) {
            unsigned long long bit0 = 1ull << (c0 & 63);
            if ((c0 < 64 ? visLo : visHi) & bit0) continue;
            int ch = c0; bool viaK1 = true; bool take = true;
            while (true) {
                unsigned long long bit = 1ull << (ch & 63);
                if (ch < 64) { if (visLo & bit) break; visLo |= bit; }
                else         { if (visHi & bit) break; visHi |= bit; }
                if (take) sM[k][sOf[k][ch]] = (unsigned char)ch;
                take = !take;
                ch = viaK1 ? sNxt[k + 1][ch] : sNxt[k][ch];
                viaK1 = !viaK1;
            }
        }
    }
    __syncthreads();

    // Phase 3: chains (64 parallel threads; slot s starts at layer-0 pair s).
    if (tid < ILG) {
        const int s = tid;
        int p = s, vch = sA[0][p];
        for (int k = 0; k < KROT; k++) {
            sPil[k][s] = (unsigned char)p;
            sVch[k][s] = (unsigned char)vch;
            if (k < KROT - 1) {
                int kn = sM[k][p];
                sKeep[k][s] = (kn == vch);
                p = sOf[k + 1][kn];
                vch = kn;
            } else sKeep[k][s] = 1;   // layer 7: keep-v form
        }
    }
    __syncthreads();

    // Phase 4: pack warp-uniform tables (128 parallel threads: (k, ilb)).
    if (tid < KROT * 16) {
        int k = tid >> 4, ilb = tid & 15;
        unsigned rv = 0, wv = 0;
        for (int st = 0; st < 4; st++) {
            int s = ilb * 4 + st;
            int pp = sPil[k][s];
            int vch = sVch[k][s];
            int partner = sA[k][pp] ^ sB[k][pp] ^ vch;
            // read = partner (fresh); write = the non-kept channel.
            int wc = sKeep[k][s] ? partner : vch;
            rv |= (unsigned)partner << (8 * st);
            wv |= (unsigned)wc << (8 * st);
        }
        g_pt4[tid] = rv;
        g_wc4[tid] = wv;
        if (k == 0) {
            unsigned v0 = 0, v7 = 0;
            for (int st = 0; st < 4; st++) {
                v0 |= (unsigned)sVch[0][ilb * 4 + st] << (8 * st);
                v7 |= (unsigned)sVch[7][ilb * 4 + st] << (8 * st);
            }
            g_v0p[ilb] = v0; g_v7p[ilb] = v7;
        }
    }

    // Phase 5: spill per-(k,slot) tables for prep_coef (512 threads, 1 each).
    {
        int k = tid >> 6, s = tid & 63;
        d_pA[k][s]    = sA[k][s];
        d_pil[k][s]   = sPil[k][s];
        d_vch[k][s]   = sVch[k][s];
        d_keepv[k][s] = sKeep[k][s];
    }
}

// ---- bake per-(layer,slot,group) pre-broadcast signed coefficients ----
// keep = sub(mul(k1,v), mul(k2,w)); write = add(mul(w1,v), mul(w2,w)).
// All four (v==a?, keepv?) orientations reduce bitwise to the reference
// sub(mul(c,xa),mul(s,xb)) / add(mul(s,xa),mul(c,xb)) via exact f16 sign
// flips and add-commutativity.
__global__ void prep_coef(const float* __restrict__ theta) {
    int idx = blockIdx.x * blockDim.x + threadIdx.x;
    if (idx >= KROT * ILG * NGRP) return;
    int g = idx & 31, s = (idx >> 5) & 63, k = idx >> 11;
    int p = d_pil[k][s];
    float t = theta[k * 2048 + g * 64 + p];        // theta[k, g*64+il]
    __half c  = __float2half(cosf(t));             // f32 trig, f16 round (ref)
    __half sn = __float2half(sinf(t));
    __half st_ = (d_vch[k][s] == d_pA[k][p]) ? sn : __hneg(sn);
    Coef4 cf;
    if (d_keepv[k][s]) {
        cf.k1 = __half2half2(c);            cf.k2 = __half2half2(st_);
        cf.w1 = __half2half2(st_);          cf.w2 = __half2half2(c);
    } else {
        cf.k1 = __half2half2(st_);          cf.k2 = __half2half2(__hneg(c));
        cf.w1 = __half2half2(c);            cf.w2 = __half2half2(__hneg(st_));
    }
    g_cs4[idx] = cf;                                // idx == (k*64+s)*32+g
}

__global__ void __launch_bounds__(TPB, 2)
rot_kernel(const float* __restrict__ x,
           const float* __restrict__ scales,
           float* __restrict__ out) {
    extern __shared__ H8 W[];                       // 4096 * 16B = 64KB
    const int tid = threadIdx.x;
    const size_t base = (size_t)blockIdx.x * (ROWS * DIMV);

    // ---- Load + transpose: global float4 -> channel-major H8 ----
    #pragma unroll
    for (int qi = 0; qi < 2; qi++) {
        int q = tid + qi * TPB;
        int gg = q >> 5, c0 = (q & 31) * 4;
        const float* p = x + base + gg * GRP + c0;
        float4 v[8];
        #pragma unroll
        for (int r = 0; r < 8; r++) v[r] = *(const float4*)(p + r * DIMV);
        const float* f = &v[0].x;
        #pragma unroll
        for (int j = 0; j < 4; j++) {
            H8 w;
            w.r01 = __floats2half2_rn(f[0*4+j], f[1*4+j]);
            w.r23 = __floats2half2_rn(f[2*4+j], f[3*4+j]);
            w.r45 = __floats2half2_rn(f[4*4+j], f[5*4+j]);
            w.r67 = __floats2half2_rn(f[6*4+j], f[7*4+j]);
            W[slot(c0 + j, gg)] = w;
        }
    }
    __syncthreads();

    // ---- Chained rotation: 4 register-resident chains per thread ----
    const int g   = tid & 31;    // lane = group
    const int ilb = tid >> 5;    // warp = slot quartet

    H8 v[4];
    {
        unsigned v0 = g_v0p[ilb];
        #pragma unroll
        for (int st = 0; st < 4; st++)
            v[st] = W[slot((v0 >> (8 * st)) & 255, g)];
    }

    #pragma unroll
    for (int k = 0; k < KROT; k++) {
        unsigned pt = g_pt4[k * 16 + ilb];          // warp-uniform read channels
        unsigned wt = g_wc4[k * 16 + ilb];          // warp-uniform write channels
        #pragma unroll
        for (int st = 0; st < 4; st++) {
            int s = ilb * 4 + st;
            Coef4 cf = g_cs4[((k * 64 + s) << 5) + g];  // coalesced LDG.128
            int pc = (pt >> (8 * st)) & 255;
            int wc = (wt >> (8 * st)) & 255;
            H8 w = W[slot(pc, g)];                      // LDS.128 (fresh: non-kept)
            H8 nv, nw;
            nv.r01 = __hsub2_rn(__hmul2_rn(cf.k1, v[st].r01), __hmul2_rn(cf.k2, w.r01));
            nw.r01 = __hadd2_rn(__hmul2_rn(cf.w1, v[st].r01), __hmul2_rn(cf.w2, w.r01));
            nv.r23 = __hsub2_rn(__hmul2_rn(cf.k1, v[st].r23), __hmul2_rn(cf.k2, w.r23));
            nw.r23 = __hadd2_rn(__hmul2_rn(cf.w1, v[st].r23), __hmul2_rn(cf.w2, w.r23));
            nv.r45 = __hsub2_rn(__hmul2_rn(cf.k1, v[st].r45), __hmul2_rn(cf.k2, w.r45));
            nw.r45 = __hadd2_rn(__hmul2_rn(cf.w1, v[st].r45), __hmul2_rn(cf.w2, w.r45));
            nv.r67 = __hsub2_rn(__hmul2_rn(cf.k1, v[st].r67), __hmul2_rn(cf.k2, w.r67));
            nw.r67 = __hadd2_rn(__hmul2_rn(cf.w1, v[st].r67), __hmul2_rn(cf.w2, w.r67));
            W[slot(wc, g)] = nw;                        // STS.128 (non-kept channel)
            v[st] = nv;                                 // register-carried (kept)
        }
        if (k == KROT - 1) {
            unsigned v7 = g_v7p[ilb];
            #pragma unroll
            for (int st = 0; st < 4; st++)
                W[slot((v7 >> (8 * st)) & 255, g)] = v[st];
        }
        __syncthreads();
    }

    // ---- Scale + transpose back + store ----
    #pragma unroll
    for (int qi = 0; qi < 2; qi++) {
        int q = tid + qi * TPB;
        int gg = q >> 5, c0 = (q & 31) * 4;
        int d = gg * GRP + c0;
        float4 sc4 = *(const float4*)(scales + d);
        const float* ps = &sc4.x;
        float o[8][4];
        #pragma unroll
        for (int j = 0; j < 4; j++) {
            H8 w = W[slot(c0 + j, gg)];
            __half2 sc2 = __half2half2(__float2half(ps[j]));  // exact
            __half2 p01 = __hmul2_rn(w.r01, sc2);
            __half2 p23 = __hmul2_rn(w.r23, sc2);
            __half2 p45 = __hmul2_rn(w.r45, sc2);
            __half2 p67 = __hmul2_rn(w.r67, sc2);
            o[0][j] = __half2float(__low2half (p01));
            o[1][j] = __half2float(__high2half(p01));
            o[2][j] = __half2float(__low2half (p23));
            o[3][j] = __half2float(__high2half(p23));
            o[4][j] = __half2float(__low2half (p45));
            o[5][j] = __half2float(__high2half(p45));
            o[6][j] = __half2float(__low2half (p67));
            o[7][j] = __half2float(__high2half(p67));
        }
        float* qp = out + base + d;
        #pragma unroll
        for (int r = 0; r < ROWS; r++)
            *(float4*)(qp + r * DIMV) = make_float4(o[r][0], o[r][1], o[r][2], o[r][3]);
    }
}

extern "C" void kernel_launch(void* const* d_in, const int* in_sizes, int n_in,
                              void* d_out, int out_size) {
    const float* x      = (const float*)d_in[0];
    const int*   pairs  = (const int*)d_in[1];
    const float* theta  = (const float*)d_in[2];
    const float* scales = (const float*)d_in[3];
    (void)n_in; (void)out_size;

    int N = in_sizes[0] / DIMV;   // 16384
    const int smem = DIMV * (int)sizeof(H8);   // 64KB dynamic
    cudaFuncSetAttribute(rot_kernel, cudaFuncAttributeMaxDynamicSharedMemorySize, smem);

    prep_sched<<<1, TPB>>>(pairs);
    prep_coef<<<(KROT * ILG * NGRP + 255) / 256, 256>>>(theta);
    rot_kernel<<<N / ROWS, TPB, smem>>>(x, scales, (float*)d_out);
}

// round 11
// speedup vs baseline: 1.4032x; 1.4032x over previous
#include <cuda_runtime.h>
#include <cuda_fp16.h>

// Inputs (harness upcasts f16 arrays to f32):
//   x[16384,4096] f32(f16-valued), pairs[8,4096] i32, theta[8,2048] f32,
//   scales[1,4096] f32, out f32.
// Reference rounds to f16 after EVERY op -> *_rn intrinsics, no contraction.
// Chained schedule (rel_err=0.0 since R8): thread keeps one rotation output in
// a register across layers (1 LDS + 1 STS per pair instead of 2+2).
// R11: walker-per-warp prep (no divergence serialization); 4B coef table
// (64KB -> L1-resident; write coefs = swap + exact sign-bit XOR, negflag in
// bit7 of write-channel byte); __ldcs/__stcs streaming hints on bulk traffic.
#define DIMV   4096
#define KROT   8
#define GRP    128
#define NGRP   32
#define ILG    64
#define ROWS   8
#define TPB    512

// ---- schedule tables consumed by prep_coef / rot_kernel ----
__device__ unsigned char d_pA[KROT][ILG];     // pair a-channel (ref orientation)
__device__ unsigned char d_pil[KROT][ILG];    // pair handled by slot s at layer k
__device__ unsigned char d_vch[KROT][ILG];    // channel held entering layer k
__device__ unsigned char d_keepv[KROT][ILG];  // keep held-side output?
__device__ unsigned g_pt4[KROT * 16];         // packed READ (partner) channels
__device__ unsigned g_wc4[KROT * 16];         // packed WRITE ch (bit7 = w-neg flag)
__device__ unsigned g_v0p[16];                // packed initial held channels
__device__ unsigned g_v7p[16];                // packed held channels at layer 7
__device__ unsigned g_kv[KROT * ILG * NGRP];  // 4B/entry: (k1,k2) as half2 bits

struct __align__(16) H8 { __half2 r01, r23, r45, r67; };  // 8 rows of a channel

// slot(c,g): conflict-free when lanes span g at warp-uniform c (rotation)
// and when lanes span c>>2 at fixed g (transpose).
__device__ __forceinline__ int slot(int c, int g) {
    return (c << 5) + (g ^ (c >> 2));
}

__device__ __forceinline__ __half2 u2h2(unsigned u) {
    return *reinterpret_cast<__half2*>(&u);
}
__device__ __forceinline__ unsigned h22u(__half2 h) {
    return *reinterpret_cast<unsigned*>(&h);
}

// ---- build chain schedule: one block; one matching walker PER WARP ----
__global__ void __launch_bounds__(TPB)
prep_sched(const int* __restrict__ pairs) {
    __shared__ unsigned char sA[KROT][ILG], sB[KROT][ILG];
    __shared__ unsigned char sOf[KROT][GRP];
    __shared__ unsigned char sNxt[KROT][GRP];   // channel -> partner channel
    __shared__ unsigned char sM[KROT][ILG];
    __shared__ unsigned char sPil[KROT][ILG], sVch[KROT][ILG], sKeep[KROT][ILG];
    const int tid = threadIdx.x;

    // Phase 1: load all pairs; build lookup tables (512 threads, 1 item each).
    {
        int k = tid >> 6, il = tid & 63;
        int a = pairs[k * DIMV + 2 * il];
        int b = pairs[k * DIMV + 2 * il + 1];
        sA[k][il] = (unsigned char)a;
        sB[k][il] = (unsigned char)b;
        sOf[k][a] = (unsigned char)il;
        sOf[k][b] = (unsigned char)il;
        sNxt[k][a] = (unsigned char)b;
        sNxt[k][b] = (unsigned char)a;
    }
    __syncthreads();

    // Phase 2: matching layer k -> k+1. ONE WALKER PER WARP (lane 0 of warps
    // 0..6) so the serial walks don't divergence-serialize inside a warp.
    // Even-cycle walk, alternating edges; visited bits in 64-bit registers.
    if ((tid & 31) == 0 && tid < (KROT - 1) * 32) {
        const int k = tid >> 5;
        unsigned long long visLo = 0ull, visHi = 0ull;
        for (int c0 = 0; c0 < GRP; c0++) {
            unsigned long long bit0 = 1ull << (c0 & 63);
            if ((c0 < 64 ? visLo : visHi) & bit0) continue;
            int ch = c0; bool viaK1 = true; bool take = true;
            while (true) {
                unsigned long long bit = 1ull << (ch & 63);
                if (ch < 64) { if (visLo & bit) break; visLo |= bit; }
                else         { if (visHi & bit) break; visHi |= bit; }
                if (take) sM[k][sOf[k][ch]] = (unsigned char)ch;
                take = !take;
                ch = viaK1 ? sNxt[k + 1][ch] : sNxt[k][ch];
                viaK1 = !viaK1;
            }
        }
    }
    __syncthreads();

    // Phase 3: chains (64 parallel threads; slot s starts at layer-0 pair s).
    if (tid < ILG) {
        const int s = tid;
        int p = s, vch = sA[0][p];
        for (int k = 0; k < KROT; k++) {
            sPil[k][s] = (unsigned char)p;
            sVch[k][s] = (unsigned char)vch;
            if (k < KROT - 1) {
                int kn = sM[k][p];
                sKeep[k][s] = (kn == vch);
                p = sOf[k + 1][kn];
                vch = kn;
            } else sKeep[k][s] = 1;   // layer 7: keep-v form
        }
    }
    __syncthreads();

    // Phase 4: pack warp-uniform tables (128 parallel threads: (k, ilb)).
    if (tid < KROT * 16) {
        int k = tid >> 4, ilb = tid & 15;
        unsigned rv = 0, wv = 0;
        for (int st = 0; st < 4; st++) {
            int s = ilb * 4 + st;
            int pp = sPil[k][s];
            int vch = sVch[k][s];
            int partner = sA[k][pp] ^ sB[k][pp] ^ vch;
            // read = partner (fresh); write = the non-kept channel;
            // bit7 of write byte = negate both write coefficients (!keepv).
            int wc = sKeep[k][s] ? partner : (vch | 0x80);
            rv |= (unsigned)partner << (8 * st);
            wv |= (unsigned)wc << (8 * st);
        }
        g_pt4[tid] = rv;
        g_wc4[tid] = wv;
        if (k == 0) {
            unsigned v0 = 0, v7 = 0;
            for (int st = 0; st < 4; st++) {
                v0 |= (unsigned)sVch[0][ilb * 4 + st] << (8 * st);
                v7 |= (unsigned)sVch[7][ilb * 4 + st] << (8 * st);
            }
            g_v0p[ilb] = v0; g_v7p[ilb] = v7;
        }
    }

    // Phase 5: spill per-(k,slot) tables for prep_coef (512 threads, 1 each).
    {
        int k = tid >> 6, s = tid & 63;
        d_pA[k][s]    = sA[k][s];
        d_pil[k][s]   = sPil[k][s];
        d_vch[k][s]   = sVch[k][s];
        d_keepv[k][s] = sKeep[k][s];
    }
}

// ---- bake per-(layer,slot,group) coefficients, 4B each (64KB, L1-resident) ----
// kv = (k1,k2); write pair = (k2^neg, k1^neg) with neg from g_wc4 bit7.
// keep  = sub(mul(k1,v), mul(k2,w)); write = add(mul(w1,v), mul(w2,w)).
// keepv:  kv=(c, s'),  neg=0 -> w=(s', c)    (reference forms directly)
// !keepv: kv=(s', -c), neg=1 -> w=(c, -s')   (exact sign-flip identities)
// Coefficient values identical to the R9/R10 bit-exact-validated ones.
__global__ void prep_coef(const float* __restrict__ theta) {
    int idx = blockIdx.x * blockDim.x + threadIdx.x;
    if (idx >= KROT * ILG * NGRP) return;
    int g = idx & 31, s = (idx >> 5) & 63, k = idx >> 11;
    int p = d_pil[k][s];
    float t = theta[k * 2048 + g * 64 + p];        // theta[k, g*64+il]
    __half c  = __float2half(cosf(t));             // f32 trig, f16 round (ref)
    __half sn = __float2half(sinf(t));
    __half st_ = (d_vch[k][s] == d_pA[k][p]) ? sn : __hneg(sn);
    __half2 kv = d_keepv[k][s] ? __halves2half2(c, st_)
                               : __halves2half2(st_, __hneg(c));
    g_kv[idx] = h22u(kv);                           // idx == (k*64+s)*32+g
}

__global__ void __launch_bounds__(TPB, 2)
rot_kernel(const float* __restrict__ x,
           const float* __restrict__ scales,
           float* __restrict__ out) {
    extern __shared__ H8 W[];                       // 4096 * 16B = 64KB
    const int tid = threadIdx.x;
    const size_t base = (size_t)blockIdx.x * (ROWS * DIMV);

    // ---- Load + transpose: streaming global float4 -> channel-major H8 ----
    #pragma unroll
    for (int qi = 0; qi < 2; qi++) {
        int q = tid + qi * TPB;
        int gg = q >> 5, c0 = (q & 31) * 4;
        const float4* p = (const float4*)(x + base + gg * GRP + c0);
        float4 v[8];
        #pragma unroll
        for (int r = 0; r < 8; r++) v[r] = __ldcs(p + r * (DIMV / 4));
        const float* f = &v[0].x;
        #pragma unroll
        for (int j = 0; j < 4; j++) {
            H8 w;
            w.r01 = __floats2half2_rn(f[0*4+j], f[1*4+j]);
            w.r23 = __floats2half2_rn(f[2*4+j], f[3*4+j]);
            w.r45 = __floats2half2_rn(f[4*4+j], f[5*4+j]);
            w.r67 = __floats2half2_rn(f[6*4+j], f[7*4+j]);
            W[slot(c0 + j, gg)] = w;
        }
    }
    __syncthreads();

    // ---- Chained rotation: 4 register-resident chains per thread ----
    const int g   = tid & 31;    // lane = group
    const int ilb = tid >> 5;    // warp = slot quartet

    H8 v[4];
    {
        unsigned v0 = g_v0p[ilb];
        #pragma unroll
        for (int st = 0; st < 4; st++)
            v[st] = W[slot((v0 >> (8 * st)) & 255, g)];
    }

    #pragma unroll
    for (int k = 0; k < KROT; k++) {
        unsigned pt = g_pt4[k * 16 + ilb];          // warp-uniform read channels
        unsigned wt = g_wc4[k * 16 + ilb];          // warp-uniform write ch + negflag
        #pragma unroll
        for (int st = 0; st < 4; st++) {
            int s = ilb * 4 + st;
            unsigned kvu = g_kv[((k * 64 + s) << 5) + g];  // LDG.32, L1-resident
            int pc  = (pt >> (8 * st)) & 255;
            int wcb = (wt >> (8 * st)) & 255;
            int wc  = wcb & 127;
            unsigned nmask = (unsigned)(wcb >> 7) * 0x80008000u;
            H8 w = W[slot(pc, g)];                      // LDS.128 (fresh: non-kept)
            __half2 kv = u2h2(kvu);
            __half2 k1 = __half2half2(__low2half(kv));
            __half2 k2 = __half2half2(__high2half(kv));
            __half2 w1 = u2h2(h22u(k2) ^ nmask);        // exact sign flips
            __half2 w2 = u2h2(h22u(k1) ^ nmask);
            H8 nv, nw;
            nv.r01 = __hsub2_rn(__hmul2_rn(k1, v[st].r01), __hmul2_rn(k2, w.r01));
            nw.r01 = __hadd2_rn(__hmul2_rn(w1, v[st].r01), __hmul2_rn(w2, w.r01));
            nv.r23 = __hsub2_rn(__hmul2_rn(k1, v[st].r23), __hmul2_rn(k2, w.r23));
            nw.r23 = __hadd2_rn(__hmul2_rn(w1, v[st].r23), __hmul2_rn(w2, w.r23));
            nv.r45 = __hsub2_rn(__hmul2_rn(k1, v[st].r45), __hmul2_rn(k2, w.r45));
            nw.r45 = __hadd2_rn(__hmul2_rn(w1, v[st].r45), __hmul2_rn(w2, w.r45));
            nv.r67 = __hsub2_rn(__hmul2_rn(k1, v[st].r67), __hmul2_rn(k2, w.r67));
            nw.r67 = __hadd2_rn(__hmul2_rn(w1, v[st].r67), __hmul2_rn(w2, w.r67));
            W[slot(wc, g)] = nw;                        // STS.128 (non-kept channel)
            v[st] = nv;                                 // register-carried (kept)
        }
        if (k == KROT - 1) {
            unsigned v7 = g_v7p[ilb];
            #pragma unroll
            for (int st = 0; st < 4; st++)
                W[slot((v7 >> (8 * st)) & 255, g)] = v[st];
        }
        __syncthreads();
    }

    // ---- Scale + transpose back + streaming store ----
    #pragma unroll
    for (int qi = 0; qi < 2; qi++) {
        int q = tid + qi * TPB;
        int gg = q >> 5, c0 = (q & 31) * 4;
        int d = gg * GRP + c0;
        float4 sc4 = *(const float4*)(scales + d);
        const float* ps = &sc4.x;
        float o[8][4];
        #pragma unroll
        for (int j = 0; j < 4; j++) {
            H8 w = W[slot(c0 + j, gg)];
            __half2 sc2 = __half2half2(__float2half(ps[j]));  // exact
            __half2 p01 = __hmul2_rn(w.r01, sc2);
            __half2 p23 = __hmul2_rn(w.r23, sc2);
            __half2 p45 = __hmul2_rn(w.r45, sc2);
            __half2 p67 = __hmul2_rn(w.r67, sc2);
            o[0][j] = __half2float(__low2half (p01));
            o[1][j] = __half2float(__high2half(p01));
            o[2][j] = __half2float(__low2half (p23));
            o[3][j] = __half2float(__high2half(p23));
            o[4][j] = __half2float(__low2half (p45));
            o[5][j] = __half2float(__high2half(p45));
            o[6][j] = __half2float(__low2half (p67));
            o[7][j] = __half2float(__high2half(p67));
        }
        float4* qp = (float4*)(out + base + d);
        #pragma unroll
        for (int r = 0; r < ROWS; r++)
            __stcs(qp + r * (DIMV / 4),
                   make_float4(o[r][0], o[r][1], o[r][2], o[r][3]));
    }
}

extern "C" void kernel_launch(void* const* d_in, const int* in_sizes, int n_in,
                              void* d_out, int out_size) {
    const float* x      = (const float*)d_in[0];
    const int*   pairs  = (const int*)d_in[1];
    const float* theta  = (const float*)d_in[2];
    const float* scales = (const float*)d_in[3];
    (void)n_in; (void)out_size;

    int N = in_sizes[0] / DIMV;   // 16384
    const int smem = DIMV * (int)sizeof(H8);   // 64KB dynamic
    cudaFuncSetAttribute(rot_kernel, cudaFuncAttributeMaxDynamicSharedMemorySize, smem);

    prep_sched<<<1, TPB>>>(pairs);
    prep_coef<<<(KROT * ILG * NGRP + 255) / 256, 256>>>(theta);
    rot_kernel<<<N / ROWS, TPB, smem>>>(x, scales, (float*)d_out);
}

// round 12
// speedup vs baseline: 1.5391x; 1.0969x over previous
#include <cuda_runtime.h>
#include <cuda_fp16.h>

// Inputs (harness upcasts f16 arrays to f32):
//   x[16384,4096] f32(f16-valued), pairs[8,4096] i32, theta[8,2048] f32,
//   scales[1,4096] f32, out f32.
// Reference rounds to f16 after EVERY op -> *_rn intrinsics, no contraction.
// Chained schedule (rel_err=0.0 since R8): thread keeps one rotation output in
// a register across layers (1 LDS + 1 STS per pair instead of 2+2).
// R12: matching computed by parallel pointer-doubling over succ2-orbits
// (each alternating cycle = two complementary orbits; take the orbit with the
// smaller min-representative). No serial walks left in prep.
#define DIMV   4096
#define KROT   8
#define GRP    128
#define NGRP   32
#define ILG    64
#define ROWS   8
#define TPB    512

// ---- schedule tables consumed by prep_coef / rot_kernel ----
__device__ unsigned char d_pA[KROT][ILG];     // pair a-channel (ref orientation)
__device__ unsigned char d_pil[KROT][ILG];    // pair handled by slot s at layer k
__device__ unsigned char d_vch[KROT][ILG];    // channel held entering layer k
__device__ unsigned char d_keepv[KROT][ILG];  // keep held-side output?
__device__ unsigned g_pt4[KROT * 16];         // packed READ (partner) channels
__device__ unsigned g_wc4[KROT * 16];         // packed WRITE ch (bit7 = w-neg flag)
__device__ unsigned g_v0p[16];                // packed initial held channels
__device__ unsigned g_v7p[16];                // packed held channels at layer 7
__device__ unsigned g_kv[KROT * ILG * NGRP];  // 4B/entry: (k1,k2) as half2 bits

struct __align__(16) H8 { __half2 r01, r23, r45, r67; };  // 8 rows of a channel

// slot(c,g): conflict-free when lanes span g at warp-uniform c (rotation)
// and when lanes span c>>2 at fixed g (transpose).
__device__ __forceinline__ int slot(int c, int g) {
    return (c << 5) + (g ^ (c >> 2));
}

__device__ __forceinline__ __half2 u2h2(unsigned u) {
    return *reinterpret_cast<__half2*>(&u);
}
__device__ __forceinline__ unsigned h22u(__half2 h) {
    return *reinterpret_cast<unsigned*>(&h);
}

#define NMATCH (KROT - 1)          // 7 matchings
#define NITEM  (NMATCH * GRP)      // 896 (layer, channel) work items

// ---- build chain schedule: one block, fully parallel matching ----
__global__ void __launch_bounds__(TPB)
prep_sched(const int* __restrict__ pairs) {
    __shared__ unsigned char sA[KROT][ILG], sB[KROT][ILG];
    __shared__ unsigned char sOf[KROT][GRP];
    __shared__ unsigned char sNxt[KROT][GRP];     // channel -> partner channel
    __shared__ unsigned char sM[KROT][ILG];
    __shared__ unsigned char sPtr[NMATCH][GRP];   // pointer-doubling succ
    __shared__ unsigned char sRep[NMATCH][GRP];   // orbit min-representative
    __shared__ unsigned char sPil[KROT][ILG], sVch[KROT][ILG], sKeep[KROT][ILG];
    const int tid = threadIdx.x;

    // Phase 1: load all pairs; build lookup tables (512 threads, 1 item each).
    {
        int k = tid >> 6, il = tid & 63;
        int a = pairs[k * DIMV + 2 * il];
        int b = pairs[k * DIMV + 2 * il + 1];
        sA[k][il] = (unsigned char)a;
        sB[k][il] = (unsigned char)b;
        sOf[k][a] = (unsigned char)il;
        sOf[k][b] = (unsigned char)il;
        sNxt[k][a] = (unsigned char)b;
        sNxt[k][b] = (unsigned char)a;
    }
    __syncthreads();

    // Phase 2a: init pointer doubling. succ2(ch) = nxt_k[ nxt_{k+1}[ch] ]
    // (the walker's 2-hop step). Orbits of succ2 = even/odd positions of the
    // alternating cycle; each cycle contributes exactly 2 complementary orbits.
    for (int it = tid; it < NITEM; it += TPB) {
        int k = it >> 7, ch = it & 127;
        sPtr[k][ch] = sNxt[k][sNxt[k + 1][ch]];
        sRep[k][ch] = (unsigned char)ch;
    }
    __syncthreads();

    // Phase 2b: 7 doubling iterations (orbit length <= 64 -> 6 suffice).
    #pragma unroll
    for (int d = 0; d < 7; d++) {
        unsigned char nr[2], np[2];
        int n = 0;
        for (int it = tid; it < NITEM; it += TPB, n++) {
            int k = it >> 7, ch = it & 127;
            int p = sPtr[k][ch];
            unsigned char rp = sRep[k][p];
            unsigned char r  = sRep[k][ch];
            nr[n] = rp < r ? rp : r;
            np[n] = sPtr[k][p];
        }
        __syncthreads();
        n = 0;
        for (int it = tid; it < NITEM; it += TPB, n++) {
            int k = it >> 7, ch = it & 127;
            sRep[k][ch] = nr[n];
            sPtr[k][ch] = np[n];
        }
        __syncthreads();
    }

    // Phase 2c: take the orbit with the smaller representative. Both channels
    // of any layer-k (and layer-k+1) pair lie in complementary orbits, so each
    // pair gets exactly one kept channel -> valid perfect matching.
    for (int it = tid; it < NITEM; it += TPB) {
        int k = it >> 7, ch = it & 127;
        int partner_orbit_rep = sRep[k][sNxt[k + 1][ch]];
        if (sRep[k][ch] < partner_orbit_rep)
            sM[k][sOf[k][ch]] = (unsigned char)ch;
    }
    __syncthreads();

    // Phase 3: chains (64 parallel threads; slot s starts at layer-0 pair s).
    if (tid < ILG) {
        const int s = tid;
        int p = s, vch = sA[0][p];
        for (int k = 0; k < KROT; k++) {
            sPil[k][s] = (unsigned char)p;
            sVch[k][s] = (unsigned char)vch;
            if (k < KROT - 1) {
                int kn = sM[k][p];
                sKeep[k][s] = (kn == vch);
                p = sOf[k + 1][kn];
                vch = kn;
            } else sKeep[k][s] = 1;   // layer 7: keep-v form
        }
    }
    __syncthreads();

    // Phase 4: pack warp-uniform tables (128 parallel threads: (k, ilb)).
    if (tid < KROT * 16) {
        int k = tid >> 4, ilb = tid & 15;
        unsigned rv = 0, wv = 0;
        for (int st = 0; st < 4; st++) {
            int s = ilb * 4 + st;
            int pp = sPil[k][s];
            int vch = sVch[k][s];
            int partner = sA[k][pp] ^ sB[k][pp] ^ vch;
            // read = partner (fresh); write = the non-kept channel;
            // bit7 of write byte = negate both write coefficients (!keepv).
            int wc = sKeep[k][s] ? partner : (vch | 0x80);
            rv |= (unsigned)partner << (8 * st);
            wv |= (unsigned)wc << (8 * st);
        }
        g_pt4[tid] = rv;
        g_wc4[tid] = wv;
        if (k == 0) {
            unsigned v0 = 0, v7 = 0;
            for (int st = 0; st < 4; st++) {
                v0 |= (unsigned)sVch[0][ilb * 4 + st] << (8 * st);
                v7 |= (unsigned)sVch[7][ilb * 4 + st] << (8 * st);
            }
            g_v0p[ilb] = v0; g_v7p[ilb] = v7;
        }
    }

    // Phase 5: spill per-(k,slot) tables for prep_coef (512 threads, 1 each).
    {
        int k = tid >> 6, s = tid & 63;
        d_pA[k][s]    = sA[k][s];
        d_pil[k][s]   = sPil[k][s];
        d_vch[k][s]   = sVch[k][s];
        d_keepv[k][s] = sKeep[k][s];
    }
}

// ---- bake per-(layer,slot,group) coefficients, 4B each (64KB, L1-resident) ----
// kv = (k1,k2); write pair = (k2^neg, k1^neg) with neg from g_wc4 bit7.
// keep  = sub(mul(k1,v), mul(k2,w)); write = add(mul(w1,v), mul(w2,w)).
// keepv:  kv=(c, s'),  neg=0 -> w=(s', c)    (reference forms directly)
// !keepv: kv=(s', -c), neg=1 -> w=(c, -s')   (exact sign-flip identities)
__global__ void prep_coef(const float* __restrict__ theta) {
    int idx = blockIdx.x * blockDim.x + threadIdx.x;
    if (idx >= KROT * ILG * NGRP) return;
    int g = idx & 31, s = (idx >> 5) & 63, k = idx >> 11;
    int p = d_pil[k][s];
    float t = theta[k * 2048 + g * 64 + p];        // theta[k, g*64+il]
    __half c  = __float2half(cosf(t));             // f32 trig, f16 round (ref)
    __half sn = __float2half(sinf(t));
    __half st_ = (d_vch[k][s] == d_pA[k][p]) ? sn : __hneg(sn);
    __half2 kv = d_keepv[k][s] ? __halves2half2(c, st_)
                               : __halves2half2(st_, __hneg(c));
    g_kv[idx] = h22u(kv);                           // idx == (k*64+s)*32+g
}

__global__ void __launch_bounds__(TPB, 2)
rot_kernel(const float* __restrict__ x,
           const float* __restrict__ scales,
           float* __restrict__ out) {
    extern __shared__ H8 W[];                       // 4096 * 16B = 64KB
    const int tid = threadIdx.x;
    const size_t base = (size_t)blockIdx.x * (ROWS * DIMV);

    // ---- Load + transpose: streaming global float4 -> channel-major H8 ----
    #pragma unroll
    for (int qi = 0; qi < 2; qi++) {
        int q = tid + qi * TPB;
        int gg = q >> 5, c0 = (q & 31) * 4;
        const float4* p = (const float4*)(x + base + gg * GRP + c0);
        float4 v[8];
        #pragma unroll
        for (int r = 0; r < 8; r++) v[r] = __ldcs(p + r * (DIMV / 4));
        const float* f = &v[0].x;
        #pragma unroll
        for (int j = 0; j < 4; j++) {
            H8 w;
            w.r01 = __floats2half2_rn(f[0*4+j], f[1*4+j]);
            w.r23 = __floats2half2_rn(f[2*4+j], f[3*4+j]);
            w.r45 = __floats2half2_rn(f[4*4+j], f[5*4+j]);
            w.r67 = __floats2half2_rn(f[6*4+j], f[7*4+j]);
            W[slot(c0 + j, gg)] = w;
        }
    }
    __syncthreads();

    // ---- Chained rotation: 4 register-resident chains per thread ----
    const int g   = tid & 31;    // lane = group
    const int ilb = tid >> 5;    // warp = slot quartet

    H8 v[4];
    {
        unsigned v0 = g_v0p[ilb];
        #pragma unroll
        for (int st = 0; st < 4; st++)
            v[st] = W[slot((v0 >> (8 * st)) & 255, g)];
    }

    #pragma unroll
    for (int k = 0; k < KROT; k++) {
        unsigned pt = g_pt4[k * 16 + ilb];          // warp-uniform read channels
        unsigned wt = g_wc4[k * 16 + ilb];          // warp-uniform write ch + negflag
        #pragma unroll
        for (int st = 0; st < 4; st++) {
            int s = ilb * 4 + st;
            unsigned kvu = g_kv[((k * 64 + s) << 5) + g];  // LDG.32, L1-resident
            int pc  = (pt >> (8 * st)) & 255;
            int wcb = (wt >> (8 * st)) & 255;
            int wc  = wcb & 127;
            unsigned nmask = (unsigned)(wcb >> 7) * 0x80008000u;
            H8 w = W[slot(pc, g)];                      // LDS.128 (fresh: non-kept)
            __half2 kv = u2h2(kvu);
            __half2 k1 = __half2half2(__low2half(kv));
            __half2 k2 = __half2half2(__high2half(kv));
            __half2 w1 = u2h2(h22u(k2) ^ nmask);        // exact sign flips
            __half2 w2 = u2h2(h22u(k1) ^ nmask);
            H8 nv, nw;
            nv.r01 = __hsub2_rn(__hmul2_rn(k1, v[st].r01), __hmul2_rn(k2, w.r01));
            nw.r01 = __hadd2_rn(__hmul2_rn(w1, v[st].r01), __hmul2_rn(w2, w.r01));
            nv.r23 = __hsub2_rn(__hmul2_rn(k1, v[st].r23), __hmul2_rn(k2, w.r23));
            nw.r23 = __hadd2_rn(__hmul2_rn(w1, v[st].r23), __hmul2_rn(w2, w.r23));
            nv.r45 = __hsub2_rn(__hmul2_rn(k1, v[st].r45), __hmul2_rn(k2, w.r45));
            nw.r45 = __hadd2_rn(__hmul2_rn(w1, v[st].r45), __hmul2_rn(w2, w.r45));
            nv.r67 = __hsub2_rn(__hmul2_rn(k1, v[st].r67), __hmul2_rn(k2, w.r67));
            nw.r67 = __hadd2_rn(__hmul2_rn(w1, v[st].r67), __hmul2_rn(w2, w.r67));
            W[slot(wc, g)] = nw;                        // STS.128 (non-kept channel)
            v[st] = nv;                                 // register-carried (kept)
        }
        if (k == KROT - 1) {
            unsigned v7 = g_v7p[ilb];
            #pragma unroll
            for (int st = 0; st < 4; st++)
                W[slot((v7 >> (8 * st)) & 255, g)] = v[st];
        }
        __syncthreads();
    }

    // ---- Scale + transpose back + streaming store ----
    #pragma unroll
    for (int qi = 0; qi < 2; qi++) {
        int q = tid + qi * TPB;
        int gg = q >> 5, c0 = (q & 31) * 4;
        int d = gg * GRP + c0;
        float4 sc4 = *(const float4*)(scales + d);
        const float* ps = &sc4.x;
        float o[8][4];
        #pragma unroll
        for (int j = 0; j < 4; j++) {
            H8 w = W[slot(c0 + j, gg)];
            __half2 sc2 = __half2half2(__float2half(ps[j]));  // exact
            __half2 p01 = __hmul2_rn(w.r01, sc2);
            __half2 p23 = __hmul2_rn(w.r23, sc2);
            __half2 p45 = __hmul2_rn(w.r45, sc2);
            __half2 p67 = __hmul2_rn(w.r67, sc2);
            o[0][j] = __half2float(__low2half (p01));
            o[1][j] = __half2float(__high2half(p01));
            o[2][j] = __half2float(__low2half (p23));
            o[3][j] = __half2float(__high2half(p23));
            o[4][j] = __half2float(__low2half (p45));
            o[5][j] = __half2float(__high2half(p45));
            o[6][j] = __half2float(__low2half (p67));
            o[7][j] = __half2float(__high2half(p67));
        }
        float4* qp = (float4*)(out + base + d);
        #pragma unroll
        for (int r = 0; r < ROWS; r++)
            __stcs(qp + r * (DIMV / 4),
                   make_float4(o[r][0], o[r][1], o[r][2], o[r][3]));
    }
}

extern "C" void kernel_launch(void* const* d_in, const int* in_sizes, int n_in,
                              void* d_out, int out_size) {
    const float* x      = (const float*)d_in[0];
    const int*   pairs  = (const int*)d_in[1];
    const float* theta  = (const float*)d_in[2];
    const float* scales = (const float*)d_in[3];
    (void)n_in; (void)out_size;

    int N = in_sizes[0] / DIMV;   // 16384
    const int smem = DIMV * (int)sizeof(H8);   // 64KB dynamic
    cudaFuncSetAttribute(rot_kernel, cudaFuncAttributeMaxDynamicSharedMemorySize, smem);

    prep_sched<<<1, TPB>>>(pairs);
    prep_coef<<<(KROT * ILG * NGRP + 255) / 256, 256>>>(theta);
    rot_kernel<<<N / ROWS, TPB, smem>>>(x, scales, (float*)d_out);
}